// round 1
// baseline (speedup 1.0000x reference)
#include <cuda_runtime.h>

// LIF layer scan: B=64, F=256, L=2048.
// out = [z (B*F*L floats), s (B*F*L floats)]
//
// Design: 128 rows per block (one b*F+f row = one serial scan), 128 blocks = 1 wave.
// Time processed in chunks of 64 steps. Input chunk staged to SMEM transposed
// [t][row] (conflict-free in scan loop), double-buffered: LDG for chunk k+1 is
// issued before computing chunk k. z/s written to SMEM transposed, then stored
// coalesced as float4.

#define BB 64
#define FF 256
#define LL 2048
#define ROWS 128
#define CHUNK 64
#define NTHREADS 256
#define PADR (ROWS + 1)   // 129: conflict-free column access in scan loop

#define BETA 15.0f
#define DT 1.0f

__global__ __launch_bounds__(NTHREADS, 1)
void lif_kernel(const float* __restrict__ I,
                const float* __restrict__ raw_tau,
                const float* __restrict__ thr_p,
                float* __restrict__ out)
{
    extern __shared__ float smem[];
    // layout: bufA[2][CHUNK][PADR], zbuf[CHUNK][PADR], sbuf[CHUNK][PADR]
    float* bufA = smem;                              // 2*CHUNK*PADR
    float* zbuf = bufA + 2 * CHUNK * PADR;           // CHUNK*PADR
    float* sbuf = zbuf + CHUNK * PADR;               // CHUNK*PADR

    const int tid = threadIdx.x;
    const int blk = blockIdx.x;
    const long long row0 = (long long)blk * ROWS;

    const float thr = thr_p[0];

    // per-compute-thread recurrent state (threads 0..ROWS-1 own one row each)
    float v = 0.0f, alpha = 0.0f, one_m_alpha = 0.0f;
    if (tid < ROWS) {
        int f = (int)((row0 + tid) % FF);
        float rt = raw_tau[f];
        // stable softplus matching jax.nn.softplus: max(x,0)+log1p(exp(-|x|))
        float sp = fmaxf(rt, 0.0f) + log1pf(expf(-fabsf(rt)));
        float tau = sp + 1e-4f;
        alpha = expf(-DT / tau);
        one_m_alpha = 1.0f - alpha;
    }
    const float beta_thr = BETA * thr;

    // Load mapping per chunk: ROWS(128) rows x 16 float4 = 2048 float4,
    // 256 threads x 8 each. idx = tid + i*256; r = idx>>4; c4 = idx&15.
    const float* Iblk = I + row0 * LL;
    float4 regs[8];

    // ---- preload chunk 0 ----
    #pragma unroll
    for (int i = 0; i < 8; i++) {
        int idx = tid + i * NTHREADS;
        int r = idx >> 4, c4 = idx & 15;
        regs[i] = *(const float4*)(Iblk + (long long)r * LL + c4 * 4);
    }
    #pragma unroll
    for (int i = 0; i < 8; i++) {
        int idx = tid + i * NTHREADS;
        int r = idx >> 4, c4 = idx & 15;
        float4 v4 = regs[i];
        bufA[(c4 * 4 + 0) * PADR + r] = v4.x;
        bufA[(c4 * 4 + 1) * PADR + r] = v4.y;
        bufA[(c4 * 4 + 2) * PADR + r] = v4.z;
        bufA[(c4 * 4 + 3) * PADR + r] = v4.w;
    }
    __syncthreads();

    float* zg = out;
    float* sg = out + (long long)BB * FF * LL;

    const int nchunks = LL / CHUNK;
    for (int k = 0; k < nchunks; k++) {
        const int t0 = k * CHUNK;

        // issue global loads for chunk k+1 (latency overlaps the scan below)
        if (k + 1 < nchunks) {
            #pragma unroll
            for (int i = 0; i < 8; i++) {
                int idx = tid + i * NTHREADS;
                int r = idx >> 4, c4 = idx & 15;
                regs[i] = *(const float4*)(Iblk + (long long)r * LL + (t0 + CHUNK) + c4 * 4);
            }
        }

        // serial scan over this chunk (threads 0..127, one row each)
        if (tid < ROWS) {
            const float* inb = bufA + (k & 1) * CHUNK * PADR;
            float vv = v;
            #pragma unroll 16
            for (int t = 0; t < CHUNK; t++) {
                float It = inb[t * PADR + tid];                  // conflict-free LDS
                float v_pre = fmaf(alpha, vv, one_m_alpha * It); // 4-cyc chain link
                bool spike = (v_pre >= thr);
                zbuf[t * PADR + tid] = fmaf(BETA, v_pre, -beta_thr);
                sbuf[t * PADR + tid] = spike ? 1.0f : 0.0f;
                vv = spike ? 0.0f : v_pre;                       // FSEL, pred-as-data
            }
            v = vv;
        }
        __syncthreads();   // z/s chunk ready; bufA[k&1] fully consumed

        // coalesced float4 stores of z/s; stash prefetched regs into other buffer
        float* nb = bufA + ((k + 1) & 1) * CHUNK * PADR;
        #pragma unroll
        for (int i = 0; i < 8; i++) {
            int idx = tid + i * NTHREADS;
            int r = idx >> 4, c4 = idx & 15;
            int cb = c4 * 4;
            float4 z4, s4;
            z4.x = zbuf[(cb + 0) * PADR + r];
            z4.y = zbuf[(cb + 1) * PADR + r];
            z4.z = zbuf[(cb + 2) * PADR + r];
            z4.w = zbuf[(cb + 3) * PADR + r];
            s4.x = sbuf[(cb + 0) * PADR + r];
            s4.y = sbuf[(cb + 1) * PADR + r];
            s4.z = sbuf[(cb + 2) * PADR + r];
            s4.w = sbuf[(cb + 3) * PADR + r];
            long long go = (row0 + r) * (long long)LL + t0 + cb;
            *(float4*)(zg + go) = z4;
            *(float4*)(sg + go) = s4;
            if (k + 1 < nchunks) {
                float4 v4 = regs[i];
                nb[(cb + 0) * PADR + r] = v4.x;
                nb[(cb + 1) * PADR + r] = v4.y;
                nb[(cb + 2) * PADR + r] = v4.z;
                nb[(cb + 3) * PADR + r] = v4.w;
            }
        }
        __syncthreads();   // stores done reading z/s; next input buffer filled
    }
}

extern "C" void kernel_launch(void* const* d_in, const int* in_sizes, int n_in,
                              void* d_out, int out_size)
{
    const float* I       = (const float*)d_in[0];
    const float* raw_tau = (const float*)d_in[1];
    const float* thr     = (const float*)d_in[2];
    float* out           = (float*)d_out;

    // dynamic smem: (2*CHUNK + 2*CHUNK) * PADR floats
    const int smem_bytes = (2 * CHUNK * PADR + 2 * CHUNK * PADR) * (int)sizeof(float);
    static bool attr_set = false;
    if (!attr_set) {
        cudaFuncSetAttribute(lif_kernel, cudaFuncAttributeMaxDynamicSharedMemorySize,
                             smem_bytes);
        attr_set = true;
    }

    const int nblocks = (BB * FF) / ROWS;  // 128
    lif_kernel<<<nblocks, NTHREADS, smem_bytes>>>(I, raw_tau, thr, out);
}

// round 2
// speedup vs baseline: 1.1934x; 1.1934x over previous
#include <cuda_runtime.h>

// LIF layer scan: B=64, F=256, L=2048.  out = [z | s], each B*F*L float32.
//
// Warp-specialized pipeline, 128 blocks (one wave), 384 threads:
//   tid   0..127 : scan warps  — one row each, serial over time, SMEM-only I/O
//   tid 128..383 : memory warps — coalesced float4 LDG/STG + SMEM transpose
// Per chunk k: scan computes chunk k while mem warps store chunk k-1 and load
// chunk k+1 (all buffers double-buffered). One __syncthreads per chunk.

#define BB 64
#define FF 256
#define LL 2048
#define ROWS 128
#define CHUNK 64
#define NTHREADS 384
#define NMEM 256
#define PADR (ROWS + 1)   // 129: conflict-free column access in scan loop

#define BETA 15.0f
#define DT 1.0f

__global__ __launch_bounds__(NTHREADS, 1)
void lif_kernel(const float* __restrict__ I,
                const float* __restrict__ raw_tau,
                const float* __restrict__ thr_p,
                float* __restrict__ out)
{
    extern __shared__ float smem[];
    float* inb = smem;                      // 2 * CHUNK * PADR
    float* zb  = inb + 2 * CHUNK * PADR;    // 2 * CHUNK * PADR
    float* sb  = zb  + 2 * CHUNK * PADR;    // 2 * CHUNK * PADR

    const int tid = threadIdx.x;
    const long long row0 = (long long)blockIdx.x * ROWS;
    const float thr = thr_p[0];

    float v = 0.0f, alpha = 0.0f, one_m_alpha = 0.0f;
    if (tid < ROWS) {
        int f = (int)((row0 + tid) % FF);
        float rt = raw_tau[f];
        // stable softplus matching jax.nn.softplus
        float sp = fmaxf(rt, 0.0f) + log1pf(expf(-fabsf(rt)));
        float tau = sp + 1e-4f;
        alpha = expf(-DT / tau);
        one_m_alpha = 1.0f - alpha;
    }
    const float beta_thr = BETA * thr;

    const float* Iblk = I + row0 * LL;
    float* zg = out;
    float* sg = out + (long long)BB * FF * LL;
    const int nchunks = LL / CHUNK;

    // ---- preload chunk 0 (mem warps) ----
    if (tid >= ROWS) {
        const int m = tid - ROWS;
        #pragma unroll
        for (int i = 0; i < 8; i++) {
            int idx = m + i * NMEM;            // 0..2047
            int r = idx >> 4, c4 = idx & 15;   // r: row 0..127, c4: float4 col
            int cb = c4 * 4;
            float4 v4 = __ldcs((const float4*)(Iblk + (long long)r * LL + cb));
            inb[(cb + 0) * PADR + r] = v4.x;
            inb[(cb + 1) * PADR + r] = v4.y;
            inb[(cb + 2) * PADR + r] = v4.z;
            inb[(cb + 3) * PADR + r] = v4.w;
        }
    }
    __syncthreads();

    for (int k = 0; k < nchunks; k++) {
        if (tid < ROWS) {
            // ---- scan warps: chunk k ----
            const float* ip = inb + (k & 1) * CHUNK * PADR + tid;
            float* zp = zb + (k & 1) * CHUNK * PADR + tid;
            float* sp = sb + (k & 1) * CHUNK * PADR + tid;
            float vv = v;
            #pragma unroll 16
            for (int t = 0; t < CHUNK; t++) {
                float It = ip[t * PADR];                          // off-chain LDS
                float v_pre = fmaf(alpha, vv, one_m_alpha * It);  // serial FFMA
                bool spike = (v_pre >= thr);
                zp[t * PADR] = fmaf(BETA, v_pre, -beta_thr);
                sp[t * PADR] = spike ? 1.0f : 0.0f;
                vv = spike ? 0.0f : v_pre;                        // FSETP+FSEL
            }
            v = vv;
        } else {
            const int m = tid - ROWS;
            // ---- mem warps: load chunk k+1 ----
            if (k + 1 < nchunks) {
                const int t0n = (k + 1) * CHUNK;
                float* d = inb + ((k + 1) & 1) * CHUNK * PADR;
                #pragma unroll
                for (int i = 0; i < 8; i++) {
                    int idx = m + i * NMEM;
                    int r = idx >> 4, c4 = idx & 15;
                    int cb = c4 * 4;
                    float4 v4 = __ldcs((const float4*)(Iblk + (long long)r * LL + t0n + cb));
                    d[(cb + 0) * PADR + r] = v4.x;
                    d[(cb + 1) * PADR + r] = v4.y;
                    d[(cb + 2) * PADR + r] = v4.z;
                    d[(cb + 3) * PADR + r] = v4.w;
                }
            }
            // ---- mem warps: store chunk k-1 ----
            if (k >= 1) {
                const int km = k - 1;
                const int t0m = km * CHUNK;
                const float* zp = zb + (km & 1) * CHUNK * PADR;
                const float* sp = sb + (km & 1) * CHUNK * PADR;
                #pragma unroll
                for (int i = 0; i < 8; i++) {
                    int idx = m + i * NMEM;
                    int r = idx >> 4, c4 = idx & 15;
                    int cb = c4 * 4;
                    float4 z4, s4;
                    z4.x = zp[(cb + 0) * PADR + r];
                    z4.y = zp[(cb + 1) * PADR + r];
                    z4.z = zp[(cb + 2) * PADR + r];
                    z4.w = zp[(cb + 3) * PADR + r];
                    s4.x = sp[(cb + 0) * PADR + r];
                    s4.y = sp[(cb + 1) * PADR + r];
                    s4.z = sp[(cb + 2) * PADR + r];
                    s4.w = sp[(cb + 3) * PADR + r];
                    long long go = (row0 + r) * (long long)LL + t0m + cb;
                    __stcs((float4*)(zg + go), z4);
                    __stcs((float4*)(sg + go), s4);
                }
            }
        }
        __syncthreads();
    }

    // ---- tail: store last chunk ----
    if (tid >= ROWS) {
        const int m = tid - ROWS;
        const int km = nchunks - 1;
        const int t0m = km * CHUNK;
        const float* zp = zb + (km & 1) * CHUNK * PADR;
        const float* sp = sb + (km & 1) * CHUNK * PADR;
        #pragma unroll
        for (int i = 0; i < 8; i++) {
            int idx = m + i * NMEM;
            int r = idx >> 4, c4 = idx & 15;
            int cb = c4 * 4;
            float4 z4, s4;
            z4.x = zp[(cb + 0) * PADR + r];
            z4.y = zp[(cb + 1) * PADR + r];
            z4.z = zp[(cb + 2) * PADR + r];
            z4.w = zp[(cb + 3) * PADR + r];
            s4.x = sp[(cb + 0) * PADR + r];
            s4.y = sp[(cb + 1) * PADR + r];
            s4.z = sp[(cb + 2) * PADR + r];
            s4.w = sp[(cb + 3) * PADR + r];
            long long go = (row0 + r) * (long long)LL + t0m + cb;
            __stcs((float4*)(zg + go), z4);
            __stcs((float4*)(sg + go), s4);
        }
    }
}

extern "C" void kernel_launch(void* const* d_in, const int* in_sizes, int n_in,
                              void* d_out, int out_size)
{
    const float* I       = (const float*)d_in[0];
    const float* raw_tau = (const float*)d_in[1];
    const float* thr     = (const float*)d_in[2];
    float* out           = (float*)d_out;

    const int smem_bytes = 6 * CHUNK * PADR * (int)sizeof(float);  // 198144
    cudaFuncSetAttribute(lif_kernel, cudaFuncAttributeMaxDynamicSharedMemorySize,
                         smem_bytes);

    const int nblocks = (BB * FF) / ROWS;  // 128
    lif_kernel<<<nblocks, NTHREADS, smem_bytes>>>(I, raw_tau, thr, out);
}

// round 3
// speedup vs baseline: 1.3148x; 1.1017x over previous
#include <cuda_runtime.h>

// LIF layer scan: B=64, F=256, L=2048.  out = [z | s], each B*F*L float32.
//
// Warp-specialized pipeline, 128 blocks (one wave), 384 threads:
//   tid   0..127 : scan warps — one row each, serial over time, SMEM-only I/O
//   tid 128..383 : mem warps  — coalesced float4 LDG/STG + swizzled SMEM transpose
// s is NOT staged: mem warps reconstruct s = (z >= 0), exactly equivalent to
// (v_pre >= thr) since z = fma(15, v_pre, -3.75) and 15*0.25 is exact.
// SMEM layout swizzle: element (r,t) -> t*128 + (r ^ 2*(t>>2)), conflict-free
// for both the scan's column access and the mem warps' half-warp transpose.

#define BB 64
#define FF 256
#define LL 2048
#define ROWS 128
#define CHUNK 64
#define NTHREADS 384
#define NMEM 256

#define BETA 15.0f
#define DT 1.0f

// swizzled scalar index inside a [CHUNK][128] tile
__device__ __forceinline__ int sidx(int t, int r) {
    return t * 128 + (r ^ (((t >> 2) << 1) & 127));
}

__global__ __launch_bounds__(NTHREADS, 1)
void lif_kernel(const float* __restrict__ I,
                const float* __restrict__ raw_tau,
                const float* __restrict__ thr_p,
                float* __restrict__ out)
{
    extern __shared__ float smem[];
    float* inb = smem;                        // 2 * CHUNK * 128
    float* zb  = inb + 2 * CHUNK * 128;       // 2 * CHUNK * 128

    const int tid = threadIdx.x;
    const long long row0 = (long long)blockIdx.x * ROWS;
    const float thr = thr_p[0];

    float v = 0.0f, alpha = 0.0f, one_m_alpha = 0.0f;
    if (tid < ROWS) {
        int f = (int)((row0 + tid) % FF);
        float rt = raw_tau[f];
        float sp = fmaxf(rt, 0.0f) + log1pf(expf(-fabsf(rt)));  // stable softplus
        float tau = sp + 1e-4f;
        alpha = expf(-DT / tau);
        one_m_alpha = 1.0f - alpha;
    }
    const float beta_thr = BETA * thr;

    const float* Iblk = I + row0 * LL;
    float* zg = out;
    float* sg = out + (long long)BB * FF * LL;
    const int nchunks = LL / CHUNK;

    // ---- preload chunk 0 (mem warps) ----
    if (tid >= ROWS) {
        const int m = tid - ROWS;
        #pragma unroll
        for (int i = 0; i < 8; i++) {
            int idx = m + i * NMEM;            // 0..2047
            int r = idx >> 4, c4 = idx & 15;
            int cb = c4 * 4;
            int rs = r ^ ((c4 << 1) & 127);    // swizzled row for this float4 col
            float4 v4 = __ldcs((const float4*)(Iblk + (long long)r * LL + cb));
            inb[(cb + 0) * 128 + rs] = v4.x;
            inb[(cb + 1) * 128 + rs] = v4.y;
            inb[(cb + 2) * 128 + rs] = v4.z;
            inb[(cb + 3) * 128 + rs] = v4.w;
        }
    }
    __syncthreads();

    for (int k = 0; k < nchunks; k++) {
        if (tid < ROWS) {
            // ---- scan warps: chunk k ----
            const float* ip = inb + (k & 1) * CHUNK * 128;
            float* zp = zb + (k & 1) * CHUNK * 128;
            float vv = v;
            #pragma unroll 16
            for (int t = 0; t < CHUNK; t++) {
                int ix = sidx(t, tid);
                float It = ip[ix];                                // off-chain LDS
                float v_pre = fmaf(alpha, vv, one_m_alpha * It);  // serial FFMA
                zp[ix] = fmaf(BETA, v_pre, -beta_thr);
                vv = (v_pre >= thr) ? 0.0f : v_pre;               // FSETP+FSEL
            }
            v = vv;
        } else {
            const int m = tid - ROWS;
            // ---- mem warps: load chunk k+1 ----
            if (k + 1 < nchunks) {
                const int t0n = (k + 1) * CHUNK;
                float* d = inb + ((k + 1) & 1) * CHUNK * 128;
                #pragma unroll
                for (int i = 0; i < 8; i++) {
                    int idx = m + i * NMEM;
                    int r = idx >> 4, c4 = idx & 15;
                    int cb = c4 * 4;
                    int rs = r ^ ((c4 << 1) & 127);
                    float4 v4 = __ldcs((const float4*)(Iblk + (long long)r * LL + t0n + cb));
                    d[(cb + 0) * 128 + rs] = v4.x;
                    d[(cb + 1) * 128 + rs] = v4.y;
                    d[(cb + 2) * 128 + rs] = v4.z;
                    d[(cb + 3) * 128 + rs] = v4.w;
                }
            }
            // ---- mem warps: store chunk k-1 (z + reconstructed s) ----
            if (k >= 1) {
                const int km = k - 1;
                const int t0m = km * CHUNK;
                const float* zp = zb + (km & 1) * CHUNK * 128;
                #pragma unroll
                for (int i = 0; i < 8; i++) {
                    int idx = m + i * NMEM;
                    int r = idx >> 4, c4 = idx & 15;
                    int cb = c4 * 4;
                    int rs = r ^ ((c4 << 1) & 127);
                    float4 z4, s4;
                    z4.x = zp[(cb + 0) * 128 + rs];
                    z4.y = zp[(cb + 1) * 128 + rs];
                    z4.z = zp[(cb + 2) * 128 + rs];
                    z4.w = zp[(cb + 3) * 128 + rs];
                    s4.x = (z4.x >= 0.0f) ? 1.0f : 0.0f;
                    s4.y = (z4.y >= 0.0f) ? 1.0f : 0.0f;
                    s4.z = (z4.z >= 0.0f) ? 1.0f : 0.0f;
                    s4.w = (z4.w >= 0.0f) ? 1.0f : 0.0f;
                    long long go = (row0 + r) * (long long)LL + t0m + cb;
                    __stcs((float4*)(zg + go), z4);
                    __stcs((float4*)(sg + go), s4);
                }
            }
        }
        __syncthreads();
    }

    // ---- tail: store last chunk ----
    if (tid >= ROWS) {
        const int m = tid - ROWS;
        const int km = nchunks - 1;
        const int t0m = km * CHUNK;
        const float* zp = zb + (km & 1) * CHUNK * 128;
        #pragma unroll
        for (int i = 0; i < 8; i++) {
            int idx = m + i * NMEM;
            int r = idx >> 4, c4 = idx & 15;
            int cb = c4 * 4;
            int rs = r ^ ((c4 << 1) & 127);
            float4 z4, s4;
            z4.x = zp[(cb + 0) * 128 + rs];
            z4.y = zp[(cb + 1) * 128 + rs];
            z4.z = zp[(cb + 2) * 128 + rs];
            z4.w = zp[(cb + 3) * 128 + rs];
            s4.x = (z4.x >= 0.0f) ? 1.0f : 0.0f;
            s4.y = (z4.y >= 0.0f) ? 1.0f : 0.0f;
            s4.z = (z4.z >= 0.0f) ? 1.0f : 0.0f;
            s4.w = (z4.w >= 0.0f) ? 1.0f : 0.0f;
            long long go = (row0 + r) * (long long)LL + t0m + cb;
            __stcs((float4*)(zg + go), z4);
            __stcs((float4*)(sg + go), s4);
        }
    }
}

extern "C" void kernel_launch(void* const* d_in, const int* in_sizes, int n_in,
                              void* d_out, int out_size)
{
    const float* I       = (const float*)d_in[0];
    const float* raw_tau = (const float*)d_in[1];
    const float* thr     = (const float*)d_in[2];
    float* out           = (float*)d_out;

    const int smem_bytes = 4 * CHUNK * 128 * (int)sizeof(float);  // 131072
    cudaFuncSetAttribute(lif_kernel, cudaFuncAttributeMaxDynamicSharedMemorySize,
                         smem_bytes);

    const int nblocks = (BB * FF) / ROWS;  // 128
    lif_kernel<<<nblocks, NTHREADS, smem_bytes>>>(I, raw_tau, thr, out);
}

// round 4
// speedup vs baseline: 1.3489x; 1.0259x over previous
#include <cuda_runtime.h>

// LIF layer scan: B=64, F=256, L=2048.  out = [z | s], each B*F*L float32.
//
// 2 CTAs per SM (grid=256, 192 threads): independent barrier domains keep the
// HBM stream continuous while the other CTA's scan warps sit in the serial chain.
//   tid  0..63  : scan warps — one row each, serial over time, SMEM-only I/O
//   tid 64..191 : mem warps  — coalesced float4 LDG/STG + swizzled SMEM transpose
// s is reconstructed as (z >= 0): exact since z = fma(15, v_pre, -3.75) and
// 15*0.25 is exactly representable.
// SMEM tile [CHUNK][64], swizzle (r,t) -> t*64 + (r ^ 2*(t>>2)): conflict-free
// for scan column access and for the mem warps' half-warp transpose.

#define BB 64
#define FF 256
#define LL 2048
#define ROWS 64
#define CHUNK 64
#define NTHREADS 192
#define NMEM 128

#define BETA 15.0f
#define DT 1.0f

__device__ __forceinline__ int sidx(int t, int r) {
    return t * 64 + (r ^ (((t >> 2) << 1) & 63));
}

__global__ __launch_bounds__(NTHREADS, 2)
void lif_kernel(const float* __restrict__ I,
                const float* __restrict__ raw_tau,
                const float* __restrict__ thr_p,
                float* __restrict__ out)
{
    extern __shared__ float smem[];
    float* inb = smem;                        // 2 * CHUNK * 64
    float* zb  = inb + 2 * CHUNK * 64;        // 2 * CHUNK * 64

    const int tid = threadIdx.x;
    const long long row0 = (long long)blockIdx.x * ROWS;
    const float thr = thr_p[0];

    float v = 0.0f, alpha = 0.0f, one_m_alpha = 0.0f;
    if (tid < ROWS) {
        int f = (int)((row0 + tid) % FF);
        float rt = raw_tau[f];
        float sp = fmaxf(rt, 0.0f) + log1pf(expf(-fabsf(rt)));  // stable softplus
        float tau = sp + 1e-4f;
        alpha = expf(-DT / tau);
        one_m_alpha = 1.0f - alpha;
    }
    const float beta_thr = BETA * thr;

    const float* Iblk = I + row0 * LL;
    float* zg = out;
    float* sg = out + (long long)BB * FF * LL;
    const int nchunks = LL / CHUNK;

    // ---- preload chunk 0 (mem warps): 64 rows x 16 float4 = 1024, 128 thr x 8 ----
    if (tid >= ROWS) {
        const int m = tid - ROWS;
        #pragma unroll
        for (int i = 0; i < 8; i++) {
            int idx = m + i * NMEM;            // 0..1023
            int r = idx >> 4, c4 = idx & 15;
            int cb = c4 * 4;
            int rs = r ^ ((c4 << 1) & 63);
            float4 v4 = __ldcs((const float4*)(Iblk + (long long)r * LL + cb));
            inb[(cb + 0) * 64 + rs] = v4.x;
            inb[(cb + 1) * 64 + rs] = v4.y;
            inb[(cb + 2) * 64 + rs] = v4.z;
            inb[(cb + 3) * 64 + rs] = v4.w;
        }
    }
    __syncthreads();

    for (int k = 0; k < nchunks; k++) {
        if (tid < ROWS) {
            // ---- scan warps: chunk k ----
            const float* ip = inb + (k & 1) * CHUNK * 64;
            float* zp = zb + (k & 1) * CHUNK * 64;
            float vv = v;
            #pragma unroll 16
            for (int t = 0; t < CHUNK; t++) {
                int ix = sidx(t, tid);
                float It = ip[ix];                                // off-chain LDS
                float v_pre = fmaf(alpha, vv, one_m_alpha * It);  // serial FFMA
                zp[ix] = fmaf(BETA, v_pre, -beta_thr);
                vv = (v_pre >= thr) ? 0.0f : v_pre;               // FSETP+FSEL
            }
            v = vv;
        } else {
            const int m = tid - ROWS;
            // ---- mem warps: load chunk k+1 ----
            if (k + 1 < nchunks) {
                const int t0n = (k + 1) * CHUNK;
                float* d = inb + ((k + 1) & 1) * CHUNK * 64;
                #pragma unroll
                for (int i = 0; i < 8; i++) {
                    int idx = m + i * NMEM;
                    int r = idx >> 4, c4 = idx & 15;
                    int cb = c4 * 4;
                    int rs = r ^ ((c4 << 1) & 63);
                    float4 v4 = __ldcs((const float4*)(Iblk + (long long)r * LL + t0n + cb));
                    d[(cb + 0) * 64 + rs] = v4.x;
                    d[(cb + 1) * 64 + rs] = v4.y;
                    d[(cb + 2) * 64 + rs] = v4.z;
                    d[(cb + 3) * 64 + rs] = v4.w;
                }
            }
            // ---- mem warps: store chunk k-1 (z + reconstructed s) ----
            if (k >= 1) {
                const int km = k - 1;
                const int t0m = km * CHUNK;
                const float* zp = zb + (km & 1) * CHUNK * 64;
                #pragma unroll
                for (int i = 0; i < 8; i++) {
                    int idx = m + i * NMEM;
                    int r = idx >> 4, c4 = idx & 15;
                    int cb = c4 * 4;
                    int rs = r ^ ((c4 << 1) & 63);
                    float4 z4, s4;
                    z4.x = zp[(cb + 0) * 64 + rs];
                    z4.y = zp[(cb + 1) * 64 + rs];
                    z4.z = zp[(cb + 2) * 64 + rs];
                    z4.w = zp[(cb + 3) * 64 + rs];
                    s4.x = (z4.x >= 0.0f) ? 1.0f : 0.0f;
                    s4.y = (z4.y >= 0.0f) ? 1.0f : 0.0f;
                    s4.z = (z4.z >= 0.0f) ? 1.0f : 0.0f;
                    s4.w = (z4.w >= 0.0f) ? 1.0f : 0.0f;
                    long long go = (row0 + r) * (long long)LL + t0m + cb;
                    __stcs((float4*)(zg + go), z4);
                    __stcs((float4*)(sg + go), s4);
                }
            }
        }
        __syncthreads();
    }

    // ---- tail: store last chunk ----
    if (tid >= ROWS) {
        const int m = tid - ROWS;
        const int km = nchunks - 1;
        const int t0m = km * CHUNK;
        const float* zp = zb + (km & 1) * CHUNK * 64;
        #pragma unroll
        for (int i = 0; i < 8; i++) {
            int idx = m + i * NMEM;
            int r = idx >> 4, c4 = idx & 15;
            int cb = c4 * 4;
            int rs = r ^ ((c4 << 1) & 63);
            float4 z4, s4;
            z4.x = zp[(cb + 0) * 64 + rs];
            z4.y = zp[(cb + 1) * 64 + rs];
            z4.z = zp[(cb + 2) * 64 + rs];
            z4.w = zp[(cb + 3) * 64 + rs];
            s4.x = (z4.x >= 0.0f) ? 1.0f : 0.0f;
            s4.y = (z4.y >= 0.0f) ? 1.0f : 0.0f;
            s4.z = (z4.z >= 0.0f) ? 1.0f : 0.0f;
            s4.w = (z4.w >= 0.0f) ? 1.0f : 0.0f;
            long long go = (row0 + r) * (long long)LL + t0m + cb;
            __stcs((float4*)(zg + go), z4);
            __stcs((float4*)(sg + go), s4);
        }
    }
}

extern "C" void kernel_launch(void* const* d_in, const int* in_sizes, int n_in,
                              void* d_out, int out_size)
{
    const float* I       = (const float*)d_in[0];
    const float* raw_tau = (const float*)d_in[1];
    const float* thr     = (const float*)d_in[2];
    float* out           = (float*)d_out;

    const int smem_bytes = 4 * CHUNK * 64 * (int)sizeof(float);  // 65536
    cudaFuncSetAttribute(lif_kernel, cudaFuncAttributeMaxDynamicSharedMemorySize,
                         smem_bytes);

    const int nblocks = (BB * FF) / ROWS;  // 256
    lif_kernel<<<nblocks, NTHREADS, smem_bytes>>>(I, raw_tau, thr, out);
}